// round 10
// baseline (speedup 1.0000x reference)
#include <cuda_runtime.h>
#include <math.h>

#define B_ 8
#define H_ 128
#define W_ 128
#define G_ 64
#define C_ 20
#define PAD_ 21
#define GRID_ (B_ * H_)

__device__ double   d_partial[GRID_][6];
__device__ int      d_nv[B_];
__device__ unsigned d_ticket;   // zero-init; self-resets via atomicInc wrap

__global__ __launch_bounds__(128) void fused_kernel(const float* __restrict__ kpt,
                                                    const float* __restrict__ preg,
                                                    const float* __restrict__ fpn,
                                                    const float* __restrict__ masks,
                                                    const float* __restrict__ gt,
                                                    const float* __restrict__ sy,
                                                    const float* __restrict__ sx,
                                                    float* __restrict__ out) {
    int bid = blockIdx.x;
    int b = bid >> 7, y = bid & 127;
    int x = threadIdx.x;

    __shared__ float4   sbox[G_];
    __shared__ float4   sGau[G_];             // (sfx, isx, eyarg, seg-as-float), row-filtered
    __shared__ int      sActG[G_];            // packed g | seg<<8
    __shared__ unsigned skp[W_];
    __shared__ float    srg[W_][PAD_];        // per-pixel per-class gaussian max
    __shared__ float    s_sfx[G_], s_isx[G_], s_eyarg[G_];
    __shared__ int      sseg[G_];
    __shared__ int      s_nAct, s_nG, s_nv, s_last;
    __shared__ float    scand[2];
    __shared__ int      scandi[2];
    __shared__ double   sacc[6][4];

    float yg = y + 0.5f, xg = x + 0.5f;

    skp[x] = 0u;
#pragma unroll
    for (int c = 0; c < C_; c++) srg[x][c] = 0.f;

    // ---- per-gt constants (threads 0..63) ----
    int kyr = -1, kxr = 0;
    float cyv = 0.f;
    if (x < G_) {
        const float* g7 = gt + (size_t)(b * G_ + x) * 7;
        float cy = g7[0], cx = g7[1];
        cyv = cy;
        sbox[x] = make_float4((g7[3] + 0.5f) * 0.25f,   // bx1
                              (g7[5] + 0.5f) * 0.25f,   // bx2
                              (g7[2] + 0.5f) * 0.25f,   // by1
                              (g7[4] + 0.5f) * 0.25f);  // by2
        s_sfx[x] = floorf((cx + 0.5f) * 0.25f);
        float dy = (float)y - floorf((cy + 0.5f) * 0.25f);
        s_eyarg[x] = -dy * dy * (0.5f / sy[b * G_ + x]);
        s_isx[x]   = 0.5f / sx[b * G_ + x];
        int cid = (int)g7[6] - 1;
        sseg[x] = (cid >= 0 && cid < C_) ? cid : C_;
        kyr = min(max((int)floorf(cy * 0.25f), 0), H_ - 1);
        kxr = min(max((int)floorf(cx * 0.25f), 0), W_ - 1);
    }
    __syncthreads();

    // ---- parallel first-occurrence argmin over 64 gts ----
    if (x < G_) {
        float v = cyv; int idx = x;
#pragma unroll
        for (int off = 16; off; off >>= 1) {
            float ov = __shfl_down_sync(0xffffffffu, v, off);
            int   oi = __shfl_down_sync(0xffffffffu, idx, off);
            if (ov < v || (ov == v && oi < idx)) { v = ov; idx = oi; }
        }
        if ((x & 31) == 0) { scand[x >> 5] = v; scandi[x >> 5] = idx; }
    }
    __syncthreads();
    if (x == 0) {
        float v0 = scand[0], v1 = scand[1];
        int   i0 = scandi[0], i1 = scandi[1];
        int am = (v1 < v0 || (v1 == v0 && i1 < i0)) ? i1 : i0;
        s_nv = am;
        s_nAct = 0;
        s_nG = 0;
        if (y == 0) d_nv[b] = am;
    }
    __syncthreads();
    int nv = s_nv;

    // ---- compaction: geometry-active + gaussian-active lists, kp scatter ----
    if (x < nv) {
        float4 bb = sbox[x];
        float t = yg - bb.z, dd = bb.w - yg;
        if (t > 0.f && dd > 0.f) {
            int a = atomicAdd(&s_nAct, 1);
            sActG[a] = x | (sseg[x] << 8);
        }
        float ea = s_eyarg[x];
        if (ea > -12.5f) {   // rows where the gaussian can exceed ~3.7e-6
            int a = atomicAdd(&s_nG, 1);
            sGau[a] = make_float4(s_sfx[x], s_isx[x], ea, __int_as_float(sseg[x]));
        }
        if (sseg[x] < C_ && kyr == y)
            atomicOr(&skp[kxr], 1u << sseg[x]);
    }
    __syncthreads();

    int nA = s_nAct, nG = s_nG;
    size_t rowoff = (size_t)bid * W_;

    // prefetch preg (overlaps geometry)
    float4 pv = __ldg(&reinterpret_cast<const float4*>(preg)[rowoff + x]);

    // ---- geometry: single pass, exact tie-merging argmin ----
    const float* mrow = masks + (rowoff + x) * G_;
    float area_min = 1e8f, loc = 0.f;
    float ml = 0.f, mr = 0.f, mt = 0.f, mb = 0.f;
    unsigned hgb = 0u;
    for (int a = 0; a < nA; a++) {
        int pk = sActG[a];
        int g = pk & 255, cg = pk >> 8;
        float4 bb = sbox[g];
        float l = xg - bb.x, r = bb.y - xg, t = yg - bb.z, d = bb.w - yg;
        float m = __ldg(&mrow[g]);
        float hm = (l > 0.f && r > 0.f) ? m : 0.f;
        loc = fmaxf(loc, hm);
        float lh = l * hm, rh = r * hm, th = t * hm, dh = d * hm;
        float ap = (lh + rh) * (th + dh) + (1.f - hm) * 1e8f;
        if (ap < area_min) {
            area_min = ap; ml = lh; mr = rh; mt = th; mb = dh; hgb = 1u << cg;
        } else if (ap == area_min) {
            ml = fmaxf(ml, lh); mr = fmaxf(mr, rh);
            mt = fmaxf(mt, th); mb = fmaxf(mb, dh);
            hgb |= 1u << cg;
        }
    }
    if (loc == 0.f) hgb = 0u;
    float dl = ml * loc, dr = mr * loc, dt = mt * loc, db = mb * loc;

    // ---- gaussian scan (row-filtered): iou_red + per-class max into own srg row ----
    float iou_red = 0.f, xf = (float)x;
    for (int a = 0; a < nG; a++) {
        float4 gp = sGau[a];
        float dxx = xf - gp.x;
        float red = __expf(fmaf(-dxx * dxx, gp.y, gp.z));
        iou_red = fmaxf(iou_red, red);
        int c = __float_as_int(gp.w);
        if (c < C_) srg[x][c] = fmaxf(srg[x][c], red);
    }
    __syncthreads();   // skp visibility (srg row is thread-private)

    // ---- IoU term ----
    float inter = (fminf(dl, pv.x) + fminf(dr, pv.y)) * (fminf(dt, pv.z) + fminf(db, pv.w));
    float uni   = (dl + dr) * (dt + db) + (pv.x + pv.y) * (pv.z + pv.w) - inter;
    float iou_t = -__logf(inter / (uni + 1e-12f) + 1e-12f) * loc * (iou_red * 4.f + 1.f);

    // ---- focal losses: thread x owns pixel x's 20 channels; 10 upfront LDG.128 ----
    float grav = 0.f, hpos = 0.f, hneg = 0.f, shg = 0.f;
    {
        const float4* kp4 = reinterpret_cast<const float4*>(kpt + (rowoff + x) * C_);
        const float4* fp4 = reinterpret_cast<const float4*>(fpn + (rowoff + x) * C_);
        float4 kv[5], fv[5];
#pragma unroll
        for (int j = 0; j < 5; j++) kv[j] = __ldg(&kp4[j]);
#pragma unroll
        for (int j = 0; j < 5; j++) fv[j] = __ldg(&fp4[j]);
        const float* ka = reinterpret_cast<const float*>(kv);
        const float* fa = reinterpret_cast<const float*>(fv);
        unsigned kb = skp[x];
#pragma unroll
        for (int c = 0; c < C_; c++) {
            float rg = srg[x][c];
            float hg = ((hgb >> c) & 1u) ? loc : 0.f;
            // gravity focal
            float p  = fminf(fmaxf(ka[c], -30.f), 30.f);
            float e1 = __expf(-p);
            float L1 = __logf(1.f + e1);            // -log_sigmoid(p)
            float iv = __fdividef(1.f, 1.f + e1);   // sigmoid(p)
            float om = e1 * iv;
            float q  = 1.f - rg; q = q * q; q = q * q;
            grav += ((kb >> c) & 1u) ? (om * om * L1)
                                     : (q * iv * iv * (p + L1));
            // heatmap focal
            float f   = fminf(fmaxf(fa[c], -30.f), 30.f);
            float e2  = __expf(-f);
            float L2  = __logf(1.f + e2);
            float iv2 = __fdividef(1.f, 1.f + e2);
            float om2 = e2 * iv2;
            hpos += om2 * om2 * L2 * hg;
            hneg += iv2 * iv2 * (f + L2);
            shg  += hg;
        }
    }

    // ---- deterministic block reduction ----
    float v[6] = { iou_t, loc, grav, hpos * 10.f, hneg * 10.f, shg };
#pragma unroll
    for (int off = 16; off; off >>= 1)
#pragma unroll
        for (int k = 0; k < 6; k++) v[k] += __shfl_down_sync(0xffffffffu, v[k], off);
    int w = x >> 5, lane = x & 31;
    __syncthreads();
    if (lane == 0)
#pragma unroll
        for (int k = 0; k < 6; k++) sacc[k][w] = (double)v[k];
    __syncthreads();
    if (x == 0) {
#pragma unroll
        for (int k = 0; k < 6; k++)
            d_partial[bid][k] = sacc[k][0] + sacc[k][1] + sacc[k][2] + sacc[k][3];
        __threadfence();
        unsigned old = atomicInc(&d_ticket, GRID_ - 1);   // wraps -> self-reset
        s_last = (old == GRID_ - 1);
    }
    __syncthreads();

    // ---- last block: deterministic final combine ----
    if (s_last) {
        __threadfence();
        int t = x;
        double tot = 0.0;
        for (int bb = 0; bb < B_; bb++) {
            double u[6];
#pragma unroll
            for (int k = 0; k < 6; k++) u[k] = d_partial[bb * H_ + t][k];
#pragma unroll
            for (int off = 16; off; off >>= 1)
#pragma unroll
                for (int k = 0; k < 6; k++) u[k] += __shfl_down_sync(0xffffffffu, u[k], off);
            __syncthreads();
            if ((t & 31) == 0)
#pragma unroll
                for (int k = 0; k < 6; k++) sacc[k][t >> 5] = u[k];
            __syncthreads();
            if (t == 0) {
                double iouS  = sacc[0][0] + sacc[0][1] + sacc[0][2] + sacc[0][3];
                double slocS = sacc[1][0] + sacc[1][1] + sacc[1][2] + sacc[1][3];
                double gravS = sacc[2][0] + sacc[2][1] + sacc[2][2] + sacc[2][3];
                double hposS = sacc[3][0] + sacc[3][1] + sacc[3][2] + sacc[3][3];
                double hnegS = sacc[4][0] + sacc[4][1] + sacc[4][2] + sacc[4][3];
                double shgS  = sacc[5][0] + sacc[5][1] + sacc[5][2] + sacc[5][3];
                double HWC = (double)(H_ * W_ * C_);
                double hm_loss = hnegS / (HWC - shgS);
                bool cond = (shgS != 0.0);
                double hm2 = hm_loss + hposS / (cond ? shgS : 1.0);
                double safe_loc = (slocS > 0.0) ? slocS : 1.0;
                double iou_out = cond ? (iouS / safe_loc) : 0.0;
                double nvf = (d_nv[bb] > 1) ? (double)d_nv[bb] : 1.0;
                double grav_out = cond ? (gravS / nvf) : 0.0;
                tot += cond ? (iou_out + grav_out + hm2) : hm_loss;
            }
        }
        if (t == 0) out[0] = (float)(tot * (1.0 / B_));
    }
}

// ---------------- launch ----------------
extern "C" void kernel_launch(void* const* d_in, const int* in_sizes, int n_in,
                              void* d_out, int out_size) {
    const float* keypoints = (const float*)d_in[0];
    const float* preg      = (const float*)d_in[1];
    const float* fpn       = (const float*)d_in[2];
    const float* gt        = (const float*)d_in[3];
    const float* masks     = (const float*)d_in[4];
    const float* sy        = (const float*)d_in[5];
    const float* sx        = (const float*)d_in[6];
    (void)in_sizes; (void)n_in; (void)out_size;

    fused_kernel<<<GRID_, 128>>>(keypoints, preg, fpn, masks, gt, sy, sx, (float*)d_out);
}

// round 11
// speedup vs baseline: 1.0475x; 1.0475x over previous
#include <cuda_runtime.h>
#include <math.h>

#define B_ 8
#define H_ 128
#define W_ 128
#define G_ 64
#define C_ 20
#define PAD_ 21                    // 20 classes + dump slot; gcd(21,32)=1 -> conflict-free
#define GRID_ (B_ * H_)
#define NT_ 256

__device__ double   d_partial[GRID_][6];
__device__ int      d_nv[B_];
__device__ unsigned d_ticket;      // zero-init; self-resets via atomicInc wrap

__global__ __launch_bounds__(NT_) void fused_kernel(const float* __restrict__ kpt,
                                                    const float* __restrict__ preg,
                                                    const float* __restrict__ fpn,
                                                    const float* __restrict__ masks,
                                                    const float* __restrict__ gt,
                                                    const float* __restrict__ sy,
                                                    const float* __restrict__ sx,
                                                    float* __restrict__ out) {
    int bid = blockIdx.x;
    int b = bid >> 7, y = bid & 127;
    int tid = threadIdx.x;
    int x = tid;                    // pixel id for tid < 128

    __shared__ float4   sbox[G_];
    __shared__ float4   sGau[G_ + 4];         // (sfx, isx, eyarg, seg-as-float), padded
    __shared__ int      sActG[G_];            // packed g | seg<<8
    __shared__ unsigned skp[W_];
    __shared__ float    srg[W_][PAD_];        // per-pixel per-class gaussian max + dump
    __shared__ float4   sPix[W_];             // (loc, hgb bits, kb bits, unused)
    __shared__ int      s_nAct, s_nG, s_nv, s_last;
    __shared__ float    scand[2];
    __shared__ int      scandi[2];
    __shared__ double   sacc[6][8];

    float yg = y + 0.5f;

    // ---- init ----
    for (int i = tid; i < W_ * PAD_; i += NT_) (&srg[0][0])[i] = 0.f;
    if (tid < W_) skp[tid] = 0u;

    // ---- per-gt constants (threads 0..63) ----
    int kyr = -1, kxr = 0;
    float cyv = 0.f;
    float gsfx = 0.f, gisx = 0.f, geyarg = 0.f; int gseg = 0;
    if (tid < G_) {
        const float* g7 = gt + (size_t)(b * G_ + tid) * 7;
        float cy = g7[0], cx = g7[1];
        cyv = cy;
        sbox[tid] = make_float4((g7[3] + 0.5f) * 0.25f,   // bx1
                                (g7[5] + 0.5f) * 0.25f,   // bx2
                                (g7[2] + 0.5f) * 0.25f,   // by1
                                (g7[4] + 0.5f) * 0.25f);  // by2
        gsfx = floorf((cx + 0.5f) * 0.25f);
        float dy = (float)y - floorf((cy + 0.5f) * 0.25f);
        geyarg = -dy * dy * (0.5f / sy[b * G_ + tid]);
        gisx   = 0.5f / sx[b * G_ + tid];
        int cid = (int)g7[6] - 1;
        gseg = (cid >= 0 && cid < C_) ? cid : C_;
        kyr = min(max((int)floorf(cy * 0.25f), 0), H_ - 1);
        kxr = min(max((int)floorf(cx * 0.25f), 0), W_ - 1);
    }

    // ---- parallel first-occurrence argmin over 64 gts ----
    if (tid < G_) {
        float v = cyv; int idx = tid;
#pragma unroll
        for (int off = 16; off; off >>= 1) {
            float ov = __shfl_down_sync(0xffffffffu, v, off);
            int   oi = __shfl_down_sync(0xffffffffu, idx, off);
            if (ov < v || (ov == v && oi < idx)) { v = ov; idx = oi; }
        }
        if ((tid & 31) == 0) { scand[tid >> 5] = v; scandi[tid >> 5] = idx; }
    }
    __syncthreads();
    if (tid == 0) {
        float v0 = scand[0], v1 = scand[1];
        int   i0 = scandi[0], i1 = scandi[1];
        int am = (v1 < v0 || (v1 == v0 && i1 < i0)) ? i1 : i0;
        s_nv = am;
        s_nAct = 0;
        s_nG = 0;
        if (y == 0) d_nv[b] = am;
    }
    __syncthreads();
    int nv = s_nv;

    // ---- compaction: geometry list + gaussian list + kp scatter ----
    if (tid < nv) {
        float4 bb = sbox[tid];
        float t = yg - bb.z, dd = bb.w - yg;
        if (t > 0.f && dd > 0.f) {
            int a = atomicAdd(&s_nAct, 1);
            sActG[a] = tid | (gseg << 8);
        }
        if (geyarg > -12.5f) {     // gaussian can exceed ~3.7e-6 on this row
            int a = atomicAdd(&s_nG, 1);
            sGau[a] = make_float4(gsfx, gisx, geyarg, __int_as_float(gseg < C_ ? gseg : C_));
        }
        if (gseg < C_ && kyr == y)
            atomicOr(&skp[kxr], 1u << gseg);
    }
    __syncthreads();
    int nA = s_nAct, nG = s_nG;
    int nG4 = (nG + 3) & ~3;
    if (tid < nG4 - nG)            // pad with harmless dummies (red = 0, dump class)
        sGau[nG + tid] = make_float4(0.f, 0.f, -1e30f, __int_as_float(C_));
    __syncthreads();

    size_t rowoff = (size_t)bid * W_;
    float iou_t = 0.f, loc = 0.f;

    if (tid < W_) {
        float xg = x + 0.5f;
        // prefetch preg (overlaps geometry)
        float4 pv = __ldg(&reinterpret_cast<const float4*>(preg)[rowoff + x]);

        // ---- geometry: single pass, exact tie-merging argmin ----
        const float* mrow = masks + (rowoff + x) * G_;
        float area_min = 1e8f;
        float ml = 0.f, mr = 0.f, mt = 0.f, mb = 0.f;
        unsigned hgb = 0u;
        for (int a = 0; a < nA; a++) {
            int pk = sActG[a];
            int g = pk & 255, cg = pk >> 8;
            float4 bb = sbox[g];
            float l = xg - bb.x, r = bb.y - xg, t = yg - bb.z, d = bb.w - yg;
            float m = __ldg(&mrow[g]);
            float hm = (l > 0.f && r > 0.f) ? m : 0.f;
            loc = fmaxf(loc, hm);
            float lh = l * hm, rh = r * hm, th = t * hm, dh = d * hm;
            float ap = (lh + rh) * (th + dh) + (1.f - hm) * 1e8f;
            if (ap < area_min) {
                area_min = ap; ml = lh; mr = rh; mt = th; mb = dh; hgb = 1u << cg;
            } else if (ap == area_min) {
                ml = fmaxf(ml, lh); mr = fmaxf(mr, rh);
                mt = fmaxf(mt, th); mb = fmaxf(mb, dh);
                hgb |= 1u << cg;
            }
        }
        if (loc == 0.f) hgb = 0u;
        float dl = ml * loc, dr = mr * loc, dt = mt * loc, db = mb * loc;

        // ---- gaussian scan: unrolled x4 over padded list ----
        float iou_red = 0.f, xf = (float)x;
        for (int a = 0; a < nG4; a += 4) {
            float4 g0 = sGau[a],     g1 = sGau[a + 1];
            float4 g2 = sGau[a + 2], g3 = sGau[a + 3];
            float d0 = xf - g0.x, d1 = xf - g1.x, d2 = xf - g2.x, d3 = xf - g3.x;
            float r0 = __expf(fmaf(-d0 * d0, g0.y, g0.z));
            float r1 = __expf(fmaf(-d1 * d1, g1.y, g1.z));
            float r2 = __expf(fmaf(-d2 * d2, g2.y, g2.z));
            float r3 = __expf(fmaf(-d3 * d3, g3.y, g3.z));
            iou_red = fmaxf(fmaxf(iou_red, fmaxf(r0, r1)), fmaxf(r2, r3));
            int c0 = __float_as_int(g0.w); srg[x][c0] = fmaxf(srg[x][c0], r0);
            int c1 = __float_as_int(g1.w); srg[x][c1] = fmaxf(srg[x][c1], r1);
            int c2 = __float_as_int(g2.w); srg[x][c2] = fmaxf(srg[x][c2], r2);
            int c3 = __float_as_int(g3.w); srg[x][c3] = fmaxf(srg[x][c3], r3);
        }

        // ---- per-pixel meta for the focal phase ----
        sPix[x] = make_float4(loc, __uint_as_float(hgb), __uint_as_float(skp[x]), 0.f);

        // ---- IoU term ----
        float inter = (fminf(dl, pv.x) + fminf(dr, pv.y)) * (fminf(dt, pv.z) + fminf(db, pv.w));
        float uni   = (dl + dr) * (dt + db) + (pv.x + pv.y) * (pv.z + pv.w) - inter;
        iou_t = -__logf(inter / (uni + 1e-12f) + 1e-12f) * loc * (iou_red * 4.f + 1.f);
    }
    __syncthreads();

    // ---- focal losses: all 256 threads; float4 j4 = xx*5 + jj stays inside pixel xx ----
    float grav = 0.f, hpos = 0.f, hneg = 0.f, shg = 0.f;
    {
        const float4* kr4 = reinterpret_cast<const float4*>(kpt + rowoff * C_);
        const float4* fr4 = reinterpret_cast<const float4*>(fpn + rowoff * C_);
        for (int j4 = tid; j4 < W_ * C_ / 4; j4 += NT_) {
            int xx = j4 / 5, jj = j4 - xx * 5;
            int c0 = jj * 4;
            float4 kv = __ldg(&kr4[j4]);
            float4 fv = __ldg(&fr4[j4]);
            float4 meta = sPix[xx];
            float locp = meta.x;
            unsigned hb = __float_as_uint(meta.y);
            unsigned kb = __float_as_uint(meta.z);
            float ka[4] = { kv.x, kv.y, kv.z, kv.w };
            float fa[4] = { fv.x, fv.y, fv.z, fv.w };
#pragma unroll
            for (int e = 0; e < 4; e++) {
                int cc = c0 + e;
                float rg = srg[xx][cc];
                float hg = ((hb >> cc) & 1u) ? locp : 0.f;
                // gravity focal
                float p  = fminf(fmaxf(ka[e], -30.f), 30.f);
                float e1 = __expf(-p);
                float L1 = __logf(1.f + e1);            // -log_sigmoid(p)
                float iv = __fdividef(1.f, 1.f + e1);   // sigmoid(p)
                float om = e1 * iv;
                float q  = 1.f - rg; q = q * q; q = q * q;
                grav += ((kb >> cc) & 1u) ? (om * om * L1)
                                          : (q * iv * iv * (p + L1));
                // heatmap focal
                float f   = fminf(fmaxf(fa[e], -30.f), 30.f);
                float e2  = __expf(-f);
                float L2  = __logf(1.f + e2);
                float iv2 = __fdividef(1.f, 1.f + e2);
                float om2 = e2 * iv2;
                hpos += om2 * om2 * L2 * hg;
                hneg += iv2 * iv2 * (f + L2);
                shg  += hg;
            }
        }
    }

    // ---- deterministic block reduction (8 warps) ----
    float v[6] = { iou_t, loc, grav, hpos * 10.f, hneg * 10.f, shg };
#pragma unroll
    for (int off = 16; off; off >>= 1)
#pragma unroll
        for (int k = 0; k < 6; k++) v[k] += __shfl_down_sync(0xffffffffu, v[k], off);
    int w = tid >> 5, lane = tid & 31;
    __syncthreads();
    if (lane == 0)
#pragma unroll
        for (int k = 0; k < 6; k++) sacc[k][w] = (double)v[k];
    __syncthreads();
    if (tid == 0) {
#pragma unroll
        for (int k = 0; k < 6; k++) {
            double t0 = sacc[k][0] + sacc[k][1] + sacc[k][2] + sacc[k][3];
            double t1 = sacc[k][4] + sacc[k][5] + sacc[k][6] + sacc[k][7];
            d_partial[bid][k] = t0 + t1;
        }
        __threadfence();
        unsigned old = atomicInc(&d_ticket, GRID_ - 1);   // wraps -> self-reset
        s_last = (old == GRID_ - 1);
    }
    __syncthreads();

    // ---- last block: deterministic final combine ----
    if (s_last) {
        __threadfence();
        int t = tid;
        double tot = 0.0;
        for (int bb = 0; bb < B_; bb++) {
            double u[6];
#pragma unroll
            for (int k = 0; k < 6; k++) u[k] = (t < H_) ? d_partial[bb * H_ + t][k] : 0.0;
#pragma unroll
            for (int off = 16; off; off >>= 1)
#pragma unroll
                for (int k = 0; k < 6; k++) u[k] += __shfl_down_sync(0xffffffffu, u[k], off);
            __syncthreads();
            if ((t & 31) == 0)
#pragma unroll
                for (int k = 0; k < 6; k++) sacc[k][t >> 5] = u[k];
            __syncthreads();
            if (t == 0) {
                double iouS = 0, slocS = 0, gravS = 0, hposS = 0, hnegS = 0, shgS = 0;
#pragma unroll
                for (int w8 = 0; w8 < 8; w8++) {
                    iouS += sacc[0][w8]; slocS += sacc[1][w8]; gravS += sacc[2][w8];
                    hposS += sacc[3][w8]; hnegS += sacc[4][w8]; shgS += sacc[5][w8];
                }
                double HWC = (double)(H_ * W_ * C_);
                double hm_loss = hnegS / (HWC - shgS);
                bool cond = (shgS != 0.0);
                double hm2 = hm_loss + hposS / (cond ? shgS : 1.0);
                double safe_loc = (slocS > 0.0) ? slocS : 1.0;
                double iou_out = cond ? (iouS / safe_loc) : 0.0;
                double nvf = (d_nv[bb] > 1) ? (double)d_nv[bb] : 1.0;
                double grav_out = cond ? (gravS / nvf) : 0.0;
                tot += cond ? (iou_out + grav_out + hm2) : hm_loss;
            }
        }
        if (t == 0) out[0] = (float)(tot * (1.0 / B_));
    }
}

// ---------------- launch ----------------
extern "C" void kernel_launch(void* const* d_in, const int* in_sizes, int n_in,
                              void* d_out, int out_size) {
    const float* keypoints = (const float*)d_in[0];
    const float* preg      = (const float*)d_in[1];
    const float* fpn       = (const float*)d_in[2];
    const float* gt        = (const float*)d_in[3];
    const float* masks     = (const float*)d_in[4];
    const float* sy        = (const float*)d_in[5];
    const float* sx        = (const float*)d_in[6];
    (void)in_sizes; (void)n_in; (void)out_size;

    fused_kernel<<<GRID_, NT_>>>(keypoints, preg, fpn, masks, gt, sy, sx, (float*)d_out);
}

// round 12
// speedup vs baseline: 1.4335x; 1.3685x over previous
#include <cuda_runtime.h>
#include <math.h>
#include <float.h>

#define B_ 8
#define H_ 128
#define W_ 128
#define G_ 64
#define C_ 20
#define PAD_ 22
#define GRID_ (B_ * H_)

__device__ double   d_partial[GRID_][6];
__device__ int      d_nv[B_];
__device__ unsigned d_ticket;   // zero-init; self-resets via atomicInc wrap

__global__ __launch_bounds__(128) void fused_kernel(const float* __restrict__ kpt,
                                                    const float* __restrict__ preg,
                                                    const float* __restrict__ fpn,
                                                    const float* __restrict__ masks,
                                                    const float* __restrict__ gt,
                                                    const float* __restrict__ sy,
                                                    const float* __restrict__ sx,
                                                    float* __restrict__ out) {
    int bid = blockIdx.x;
    int b = bid >> 7, y = bid & 127;
    int x = threadIdx.x;

    __shared__ float4   sbox[G_];
    __shared__ float4   sGau[G_ + 2];         // (sfx, isx, eyarg, class bits) row-filtered + pad
    __shared__ int      sseg[G_];
    __shared__ int      sActG[G_];            // packed g | seg<<8
    __shared__ unsigned skp[W_], shgb[W_];
    __shared__ float    sloc[W_];
    __shared__ float    srg[W_][PAD_];        // per-pixel per-class gaussian max (+ dump slot 20)
    __shared__ int      s_nAct, s_nG, s_nv, s_last;
    __shared__ float    scand[2];
    __shared__ int      scandi[2];
    __shared__ double   sacc[6][4];

    float yg = y + 0.5f, xg = x + 0.5f;

    // ---- phase A: init + per-gt constants ----
    skp[x] = 0u;
#pragma unroll
    for (int c = 0; c <= C_; c++) srg[x][c] = 0.f;

    int kyr = -1, kxr = 0;
    float cyv = 0.f;
    float gsfx = 0.f, gisx = 0.f, geyarg = -1e30f;
    if (x < G_) {
        const float* g7 = gt + (size_t)(b * G_ + x) * 7;
        float cy = g7[0], cx = g7[1];
        cyv = cy;
        sbox[x] = make_float4((g7[3] + 0.5f) * 0.25f,   // bx1
                              (g7[5] + 0.5f) * 0.25f,   // bx2
                              (g7[2] + 0.5f) * 0.25f,   // by1
                              (g7[4] + 0.5f) * 0.25f);  // by2
        gsfx = floorf((cx + 0.5f) * 0.25f);
        float dy = (float)y - floorf((cy + 0.5f) * 0.25f);
        geyarg = -dy * dy * (0.5f / sy[b * G_ + x]);
        gisx   = 0.5f / sx[b * G_ + x];
        int cid = (int)g7[6] - 1;
        sseg[x] = (cid >= 0 && cid < C_) ? cid : C_;
        kyr = min(max((int)floorf(cy * 0.25f), 0), H_ - 1);
        kxr = min(max((int)floorf(cx * 0.25f), 0), W_ - 1);
    }
    __syncthreads();

    // ---- parallel first-occurrence argmin over 64 gts ----
    if (x < G_) {
        float v = cyv; int idx = x;
#pragma unroll
        for (int off = 16; off; off >>= 1) {
            float ov = __shfl_down_sync(0xffffffffu, v, off);
            int   oi = __shfl_down_sync(0xffffffffu, idx, off);
            if (ov < v || (ov == v && oi < idx)) { v = ov; idx = oi; }
        }
        if ((x & 31) == 0) { scand[x >> 5] = v; scandi[x >> 5] = idx; }
    }
    __syncthreads();
    if (x == 0) {
        float v0 = scand[0], v1 = scand[1];
        int   i0 = scandi[0], i1 = scandi[1];
        int am = (v1 < v0 || (v1 == v0 && i1 < i0)) ? i1 : i0;
        s_nv = am;
        s_nAct = 0;
        s_nG = 0;
        if (y == 0) d_nv[b] = am;
    }
    __syncthreads();
    int nv = s_nv;

    // ---- compaction: geometry list + row-filtered gaussian list + kp scatter ----
    if (x < nv) {
        float4 bb = sbox[x];
        float t = yg - bb.z, dd = bb.w - yg;
        if (t > 0.f && dd > 0.f) {
            int a = atomicAdd(&s_nAct, 1);
            sActG[a] = x | (sseg[x] << 8);
        }
        if (geyarg > -12.5f) {    // gaussian can exceed ~3.7e-6 on this row
            int a = atomicAdd(&s_nG, 1);
            // class clamped to dump slot 20 for invalid-class gts
            int cc = sseg[x] < C_ ? sseg[x] : C_;
            sGau[a] = make_float4(gsfx, gisx, geyarg, __int_as_float(cc));
        }
        if (sseg[x] < C_ && kyr == y)
            atomicOr(&skp[kxr], 1u << sseg[x]);
    }
    __syncthreads();

    int nA = s_nAct, nG = s_nG;
    int nG2 = (nG + 1) & ~1;
    if (x < nG2 - nG)             // one dummy to make the count even (red = 0, dump class)
        sGau[nG + x] = make_float4(0.f, 0.f, -1e30f, __int_as_float(C_));
    __syncthreads();

    size_t rowoff = (size_t)bid * W_;

    // ---- geometry: single pass with exact tie-merging argmin (identical to R6) ----
    const float* mrow = masks + (rowoff + x) * G_;
    float area_min = 1e8f, loc = 0.f;
    float ml = 0.f, mr = 0.f, mt = 0.f, mb = 0.f;
    unsigned hgb = 0u;
    for (int a = 0; a < nA; a++) {
        int pk = sActG[a];
        int g = pk & 255, cg = pk >> 8;
        float4 bb = sbox[g];
        float l = xg - bb.x, r = bb.y - xg, t = yg - bb.z, d = bb.w - yg;
        float m = __ldg(&mrow[g]);
        float hm = (l > 0.f && r > 0.f) ? m : 0.f;
        loc = fmaxf(loc, hm);
        float lh = l * hm, rh = r * hm, th = t * hm, dh = d * hm;
        float ap = (lh + rh) * (th + dh) + (1.f - hm) * 1e8f;
        if (ap < area_min) {
            area_min = ap; ml = lh; mr = rh; mt = th; mb = dh; hgb = 1u << cg;
        } else if (ap == area_min) {
            ml = fmaxf(ml, lh); mr = fmaxf(mr, rh);
            mt = fmaxf(mt, th); mb = fmaxf(mb, dh);
            hgb |= 1u << cg;
        }
    }
    if (loc == 0.f) hgb = 0u;
    float dl = ml * loc, dr = mr * loc, dt = mt * loc, db = mb * loc;

    // ---- gaussian scan: filtered + x2 unrolled, branch-free dump-slot writes ----
    float iou_red = 0.f, xf = (float)x;
    for (int a = 0; a < nG2; a += 2) {
        float4 g0 = sGau[a], g1 = sGau[a + 1];
        float d0 = xf - g0.x, d1 = xf - g1.x;
        float r0 = __expf(fmaf(-d0 * d0, g0.y, g0.z));
        float r1 = __expf(fmaf(-d1 * d1, g1.y, g1.z));
        iou_red = fmaxf(iou_red, fmaxf(r0, r1));
        int c0 = __float_as_int(g0.w);
        int c1 = __float_as_int(g1.w);
        srg[x][c0] = fmaxf(srg[x][c0], r0);
        srg[x][c1] = fmaxf(srg[x][c1], r1);
    }
    sloc[x] = loc;
    shgb[x] = hgb;
    __syncthreads();

    // ---- IoU term (thread = pixel x) ----
    float4 pv = reinterpret_cast<const float4*>(preg)[rowoff + x];
    float inter = (fminf(dl, pv.x) + fminf(dr, pv.y)) * (fminf(dt, pv.z) + fminf(db, pv.w));
    float uni   = (dl + dr) * (dt + db) + (pv.x + pv.y) * (pv.z + pv.w) - inter;
    float iou_t = -__logf(inter / (uni + 1e-12f) + 1e-12f) * loc * (iou_red * 4.f + 1.f);

    // ---- focal losses: flat coalesced loop over W*C elements (identical to R6) ----
    float grav = 0.f, hpos = 0.f, hneg = 0.f, shg = 0.f;
    const float4* kr4 = reinterpret_cast<const float4*>(kpt + rowoff * C_);
    const float4* fr4 = reinterpret_cast<const float4*>(fpn + rowoff * C_);
#pragma unroll
    for (int ch = 0; ch < (W_ * C_ / 4) / 128; ch++) {
        int i4 = ch * 128 + x;
        float4 kv = __ldg(&kr4[i4]);
        float4 fv = __ldg(&fr4[i4]);
        float ka[4] = { kv.x, kv.y, kv.z, kv.w };
        float fa[4] = { fv.x, fv.y, fv.z, fv.w };
#pragma unroll
        for (int e = 0; e < 4; e++) {
            int i = i4 * 4 + e;
            int xx = i / C_, cc = i - xx * C_;
            float rg = srg[xx][cc];
            float hg = ((shgb[xx] >> cc) & 1u) ? sloc[xx] : 0.f;
            // gravity focal
            float p  = fminf(fmaxf(ka[e], -30.f), 30.f);
            float e1 = __expf(-p);
            float L1 = __logf(1.f + e1);
            float iv = __fdividef(1.f, 1.f + e1);
            float om = e1 * iv;
            float q  = 1.f - rg; q = q * q; q = q * q;
            grav += ((skp[xx] >> cc) & 1u) ? (om * om * L1)
                                           : (q * iv * iv * (p + L1));
            // heatmap focal
            float f   = fminf(fmaxf(fa[e], -30.f), 30.f);
            float e2  = __expf(-f);
            float L2  = __logf(1.f + e2);
            float iv2 = __fdividef(1.f, 1.f + e2);
            float om2 = e2 * iv2;
            hpos += om2 * om2 * L2 * hg;
            hneg += iv2 * iv2 * (f + L2);
            shg  += hg;
        }
    }

    // ---- deterministic block reduction ----
    float v[6] = { iou_t, loc, grav, hpos * 10.f, hneg * 10.f, shg };
#pragma unroll
    for (int off = 16; off; off >>= 1)
#pragma unroll
        for (int k = 0; k < 6; k++) v[k] += __shfl_down_sync(0xffffffffu, v[k], off);
    int w = x >> 5, lane = x & 31;
    __syncthreads();
    if (lane == 0)
#pragma unroll
        for (int k = 0; k < 6; k++) sacc[k][w] = (double)v[k];
    __syncthreads();
    if (x == 0) {
#pragma unroll
        for (int k = 0; k < 6; k++)
            d_partial[bid][k] = sacc[k][0] + sacc[k][1] + sacc[k][2] + sacc[k][3];
        __threadfence();
        unsigned old = atomicInc(&d_ticket, GRID_ - 1);   // wraps -> self-reset
        s_last = (old == GRID_ - 1);
    }
    __syncthreads();

    // ---- last block: deterministic final combine ----
    if (s_last) {
        __threadfence();
        int t = x;
        double tot = 0.0;
        for (int bb = 0; bb < B_; bb++) {
            double u[6];
#pragma unroll
            for (int k = 0; k < 6; k++) u[k] = d_partial[bb * H_ + t][k];
#pragma unroll
            for (int off = 16; off; off >>= 1)
#pragma unroll
                for (int k = 0; k < 6; k++) u[k] += __shfl_down_sync(0xffffffffu, u[k], off);
            __syncthreads();
            if ((t & 31) == 0)
#pragma unroll
                for (int k = 0; k < 6; k++) sacc[k][t >> 5] = u[k];
            __syncthreads();
            if (t == 0) {
                double iouS  = sacc[0][0] + sacc[0][1] + sacc[0][2] + sacc[0][3];
                double slocS = sacc[1][0] + sacc[1][1] + sacc[1][2] + sacc[1][3];
                double gravS = sacc[2][0] + sacc[2][1] + sacc[2][2] + sacc[2][3];
                double hposS = sacc[3][0] + sacc[3][1] + sacc[3][2] + sacc[3][3];
                double hnegS = sacc[4][0] + sacc[4][1] + sacc[4][2] + sacc[4][3];
                double shgS  = sacc[5][0] + sacc[5][1] + sacc[5][2] + sacc[5][3];
                double HWC = (double)(H_ * W_ * C_);
                double hm_loss = hnegS / (HWC - shgS);
                bool cond = (shgS != 0.0);
                double hm2 = hm_loss + hposS / (cond ? shgS : 1.0);
                double safe_loc = (slocS > 0.0) ? slocS : 1.0;
                double iou_out = cond ? (iouS / safe_loc) : 0.0;
                double nvf = (d_nv[bb] > 1) ? (double)d_nv[bb] : 1.0;
                double grav_out = cond ? (gravS / nvf) : 0.0;
                tot += cond ? (iou_out + grav_out + hm2) : hm_loss;
            }
        }
        if (t == 0) out[0] = (float)(tot * (1.0 / B_));
    }
}

// ---------------- launch ----------------
extern "C" void kernel_launch(void* const* d_in, const int* in_sizes, int n_in,
                              void* d_out, int out_size) {
    const float* keypoints = (const float*)d_in[0];
    const float* preg      = (const float*)d_in[1];
    const float* fpn       = (const float*)d_in[2];
    const float* gt        = (const float*)d_in[3];
    const float* masks     = (const float*)d_in[4];
    const float* sy        = (const float*)d_in[5];
    const float* sx        = (const float*)d_in[6];
    (void)in_sizes; (void)n_in; (void)out_size;

    fused_kernel<<<GRID_, 128>>>(keypoints, preg, fpn, masks, gt, sy, sx, (float*)d_out);
}

// round 14
// speedup vs baseline: 1.5447x; 1.0775x over previous
#include <cuda_runtime.h>
#include <math.h>
#include <float.h>

#define B_ 8
#define H_ 128
#define W_ 128
#define G_ 64
#define C_ 20
#define PAD_ 22
#define GRID_ (B_ * H_)

__device__ double   d_partial[GRID_][6];
__device__ int      d_nv[B_];
__device__ unsigned d_ticket;   // zero-init; self-resets via atomicInc wrap

// one focal float4-pair: 4 channels of kpt/fpn at flat element block i4
__device__ __forceinline__ void focal4(float4 kv, float4 fv, int i4,
                                       const float srg_[][PAD_],
                                       const unsigned* __restrict__ shgb,
                                       const float* __restrict__ sloc,
                                       const unsigned* __restrict__ skp,
                                       float& grav, float& hpos, float& hneg, float& shg) {
#pragma unroll
    for (int e = 0; e < 4; e++) {
        int i = i4 * 4 + e;
        int xx = i / C_, cc = i - xx * C_;
        float ka = (e == 0) ? kv.x : (e == 1) ? kv.y : (e == 2) ? kv.z : kv.w;
        float fa = (e == 0) ? fv.x : (e == 1) ? fv.y : (e == 2) ? fv.z : fv.w;
        float rg = srg_[xx][cc];
        float hg = ((shgb[xx] >> cc) & 1u) ? sloc[xx] : 0.f;
        // gravity focal
        float p  = fminf(fmaxf(ka, -30.f), 30.f);
        float e1 = __expf(-p);
        float L1 = __logf(1.f + e1);            // -log_sigmoid(p)
        float iv = __fdividef(1.f, 1.f + e1);   // sigmoid(p)
        float om = e1 * iv;
        float q  = 1.f - rg; q = q * q; q = q * q;
        grav += ((skp[xx] >> cc) & 1u) ? (om * om * L1)
                                       : (q * iv * iv * (p + L1));
        // heatmap focal
        float f   = fminf(fmaxf(fa, -30.f), 30.f);
        float e2  = __expf(-f);
        float L2  = __logf(1.f + e2);
        float iv2 = __fdividef(1.f, 1.f + e2);
        float om2 = e2 * iv2;
        hpos += om2 * om2 * L2 * hg;
        hneg += iv2 * iv2 * (f + L2);
        shg  += hg;
    }
}

__global__ __launch_bounds__(128, 7) void fused_kernel(const float* __restrict__ kpt,
                                                       const float* __restrict__ preg,
                                                       const float* __restrict__ fpn,
                                                       const float* __restrict__ masks,
                                                       const float* __restrict__ gt,
                                                       const float* __restrict__ sy,
                                                       const float* __restrict__ sx,
                                                       float* __restrict__ out) {
    int bid = blockIdx.x;
    int b = bid >> 7, y = bid & 127;
    int x = threadIdx.x;

    __shared__ float4   sbox[G_];
    __shared__ float4   sGau[G_ + 2];         // (sfx, isx, eyarg, class bits) row-filtered + pad
    __shared__ int      sseg[G_];
    __shared__ int      sActG[G_];            // packed g | seg<<8
    __shared__ unsigned skp[W_], shgb[W_];
    __shared__ float    sloc[W_];
    __shared__ float    srg[W_][PAD_];        // per-pixel per-class gaussian max (+ dump slot 20)
    __shared__ int      s_nAct, s_nG, s_nv, s_last;
    __shared__ float    scand[2];
    __shared__ int      scandi[2];
    __shared__ double   sacc[6][4];

    float yg = y + 0.5f, xg = x + 0.5f;

    // ---- phase A: init + per-gt constants ----
    skp[x] = 0u;
#pragma unroll
    for (int c = 0; c <= C_; c++) srg[x][c] = 0.f;

    int kyr = -1, kxr = 0;
    float cyv = 0.f;
    float gsfx = 0.f, gisx = 0.f, geyarg = -1e30f;
    if (x < G_) {
        const float* g7 = gt + (size_t)(b * G_ + x) * 7;
        float cy = g7[0], cx = g7[1];
        cyv = cy;
        sbox[x] = make_float4((g7[3] + 0.5f) * 0.25f,   // bx1
                              (g7[5] + 0.5f) * 0.25f,   // bx2
                              (g7[2] + 0.5f) * 0.25f,   // by1
                              (g7[4] + 0.5f) * 0.25f);  // by2
        gsfx = floorf((cx + 0.5f) * 0.25f);
        float dy = (float)y - floorf((cy + 0.5f) * 0.25f);
        geyarg = -dy * dy * (0.5f / sy[b * G_ + x]);
        gisx   = 0.5f / sx[b * G_ + x];
        int cid = (int)g7[6] - 1;
        sseg[x] = (cid >= 0 && cid < C_) ? cid : C_;
        kyr = min(max((int)floorf(cy * 0.25f), 0), H_ - 1);
        kxr = min(max((int)floorf(cx * 0.25f), 0), W_ - 1);
    }
    __syncthreads();

    // ---- parallel first-occurrence argmin over 64 gts ----
    if (x < G_) {
        float v = cyv; int idx = x;
#pragma unroll
        for (int off = 16; off; off >>= 1) {
            float ov = __shfl_down_sync(0xffffffffu, v, off);
            int   oi = __shfl_down_sync(0xffffffffu, idx, off);
            if (ov < v || (ov == v && oi < idx)) { v = ov; idx = oi; }
        }
        if ((x & 31) == 0) { scand[x >> 5] = v; scandi[x >> 5] = idx; }
    }
    __syncthreads();
    if (x == 0) {
        float v0 = scand[0], v1 = scand[1];
        int   i0 = scandi[0], i1 = scandi[1];
        int am = (v1 < v0 || (v1 == v0 && i1 < i0)) ? i1 : i0;
        s_nv = am;
        s_nAct = 0;
        s_nG = 0;
        if (y == 0) d_nv[b] = am;
    }
    __syncthreads();
    int nv = s_nv;

    // ---- compaction: geometry list + row-filtered gaussian list + kp scatter ----
    if (x < nv) {
        float4 bb = sbox[x];
        float t = yg - bb.z, dd = bb.w - yg;
        if (t > 0.f && dd > 0.f) {
            int a = atomicAdd(&s_nAct, 1);
            sActG[a] = x | (sseg[x] << 8);
        }
        if (geyarg > -12.5f) {    // gaussian can exceed ~3.7e-6 on this row
            int a = atomicAdd(&s_nG, 1);
            int cc = sseg[x] < C_ ? sseg[x] : C_;
            sGau[a] = make_float4(gsfx, gisx, geyarg, __int_as_float(cc));
        }
        if (sseg[x] < C_ && kyr == y)
            atomicOr(&skp[kxr], 1u << sseg[x]);
    }
    __syncthreads();

    int nA = s_nAct, nG = s_nG;
    int nG2 = (nG + 1) & ~1;
    if (x < nG2 - nG)             // one dummy to make the count even (red = 0, dump class)
        sGau[nG + x] = make_float4(0.f, 0.f, -1e30f, __int_as_float(C_));
    __syncthreads();

    size_t rowoff = (size_t)bid * W_;

    // ---- geometry: single pass with exact tie-merging argmin ----
    const float* mrow = masks + (rowoff + x) * G_;
    float area_min = 1e8f, loc = 0.f;
    float ml = 0.f, mr = 0.f, mt = 0.f, mb = 0.f;
    unsigned hgb = 0u;
    for (int a = 0; a < nA; a++) {
        int pk = sActG[a];
        int g = pk & 255, cg = pk >> 8;
        float4 bb = sbox[g];
        float l = xg - bb.x, r = bb.y - xg, t = yg - bb.z, d = bb.w - yg;
        float m = __ldg(&mrow[g]);
        float hm = (l > 0.f && r > 0.f) ? m : 0.f;
        loc = fmaxf(loc, hm);
        float lh = l * hm, rh = r * hm, th = t * hm, dh = d * hm;
        float ap = (lh + rh) * (th + dh) + (1.f - hm) * 1e8f;
        if (ap < area_min) {
            area_min = ap; ml = lh; mr = rh; mt = th; mb = dh; hgb = 1u << cg;
        } else if (ap == area_min) {
            ml = fmaxf(ml, lh); mr = fmaxf(mr, rh);
            mt = fmaxf(mt, th); mb = fmaxf(mb, dh);
            hgb |= 1u << cg;
        }
    }
    if (loc == 0.f) hgb = 0u;
    float dl = ml * loc, dr = mr * loc, dt = mt * loc, db = mb * loc;

    // ---- gaussian scan: filtered + x2 unrolled, branch-free dump-slot writes ----
    float iou_red = 0.f, xf = (float)x;
    for (int a = 0; a < nG2; a += 2) {
        float4 g0 = sGau[a], g1 = sGau[a + 1];
        float d0 = xf - g0.x, d1 = xf - g1.x;
        float r0 = __expf(fmaf(-d0 * d0, g0.y, g0.z));
        float r1 = __expf(fmaf(-d1 * d1, g1.y, g1.z));
        iou_red = fmaxf(iou_red, fmaxf(r0, r1));
        int c0 = __float_as_int(g0.w);
        int c1 = __float_as_int(g1.w);
        srg[x][c0] = fmaxf(srg[x][c0], r0);
        srg[x][c1] = fmaxf(srg[x][c1], r1);
    }
    sloc[x] = loc;
    shgb[x] = hgb;
    __syncthreads();

    // ---- IoU term (thread = pixel x) ----
    float4 pv = reinterpret_cast<const float4*>(preg)[rowoff + x];
    float inter = (fminf(dl, pv.x) + fminf(dr, pv.y)) * (fminf(dt, pv.z) + fminf(db, pv.w));
    float uni   = (dl + dr) * (dt + db) + (pv.x + pv.y) * (pv.z + pv.w) - inter;
    float iou_t = -__logf(inter / (uni + 1e-12f) + 1e-12f) * loc * (iou_red * 4.f + 1.f);

    // ---- focal losses: hoist ALL 10 LDG.128 upfront (MLP=10), then 5 chunk bodies ----
    float grav = 0.f, hpos = 0.f, hneg = 0.f, shg = 0.f;
    {
        const float4* kr4 = reinterpret_cast<const float4*>(kpt + rowoff * C_);
        const float4* fr4 = reinterpret_cast<const float4*>(fpn + rowoff * C_);
        float4 kv0 = __ldg(&kr4[          x]);
        float4 kv1 = __ldg(&kr4[128     + x]);
        float4 kv2 = __ldg(&kr4[256     + x]);
        float4 kv3 = __ldg(&kr4[384     + x]);
        float4 kv4 = __ldg(&kr4[512     + x]);
        float4 fv0 = __ldg(&fr4[          x]);
        float4 fv1 = __ldg(&fr4[128     + x]);
        float4 fv2 = __ldg(&fr4[256     + x]);
        float4 fv3 = __ldg(&fr4[384     + x]);
        float4 fv4 = __ldg(&fr4[512     + x]);
        focal4(kv0, fv0,       x, srg, shgb, sloc, skp, grav, hpos, hneg, shg);
        focal4(kv1, fv1, 128 + x, srg, shgb, sloc, skp, grav, hpos, hneg, shg);
        focal4(kv2, fv2, 256 + x, srg, shgb, sloc, skp, grav, hpos, hneg, shg);
        focal4(kv3, fv3, 384 + x, srg, shgb, sloc, skp, grav, hpos, hneg, shg);
        focal4(kv4, fv4, 512 + x, srg, shgb, sloc, skp, grav, hpos, hneg, shg);
    }

    // ---- deterministic block reduction ----
    float v[6] = { iou_t, loc, grav, hpos * 10.f, hneg * 10.f, shg };
#pragma unroll
    for (int off = 16; off; off >>= 1)
#pragma unroll
        for (int k = 0; k < 6; k++) v[k] += __shfl_down_sync(0xffffffffu, v[k], off);
    int w = x >> 5, lane = x & 31;
    __syncthreads();
    if (lane == 0)
#pragma unroll
        for (int k = 0; k < 6; k++) sacc[k][w] = (double)v[k];
    __syncthreads();
    if (x == 0) {
#pragma unroll
        for (int k = 0; k < 6; k++)
            d_partial[bid][k] = sacc[k][0] + sacc[k][1] + sacc[k][2] + sacc[k][3];
        __threadfence();
        unsigned old = atomicInc(&d_ticket, GRID_ - 1);   // wraps -> self-reset
        s_last = (old == GRID_ - 1);
    }
    __syncthreads();

    // ---- last block: deterministic final combine ----
    if (s_last) {
        __threadfence();
        int t = x;
        double tot = 0.0;
        for (int bb = 0; bb < B_; bb++) {
            double u[6];
#pragma unroll
            for (int k = 0; k < 6; k++) u[k] = d_partial[bb * H_ + t][k];
#pragma unroll
            for (int off = 16; off; off >>= 1)
#pragma unroll
                for (int k = 0; k < 6; k++) u[k] += __shfl_down_sync(0xffffffffu, u[k], off);
            __syncthreads();
            if ((t & 31) == 0)
#pragma unroll
                for (int k = 0; k < 6; k++) sacc[k][t >> 5] = u[k];
            __syncthreads();
            if (t == 0) {
                double iouS  = sacc[0][0] + sacc[0][1] + sacc[0][2] + sacc[0][3];
                double slocS = sacc[1][0] + sacc[1][1] + sacc[1][2] + sacc[1][3];
                double gravS = sacc[2][0] + sacc[2][1] + sacc[2][2] + sacc[2][3];
                double hposS = sacc[3][0] + sacc[3][1] + sacc[3][2] + sacc[3][3];
                double hnegS = sacc[4][0] + sacc[4][1] + sacc[4][2] + sacc[4][3];
                double shgS  = sacc[5][0] + sacc[5][1] + sacc[5][2] + sacc[5][3];
                double HWC = (double)(H_ * W_ * C_);
                double hm_loss = hnegS / (HWC - shgS);
                bool cond = (shgS != 0.0);
                double hm2 = hm_loss + hposS / (cond ? shgS : 1.0);
                double safe_loc = (slocS > 0.0) ? slocS : 1.0;
                double iou_out = cond ? (iouS / safe_loc) : 0.0;
                double nvf = (d_nv[bb] > 1) ? (double)d_nv[bb] : 1.0;
                double grav_out = cond ? (gravS / nvf) : 0.0;
                tot += cond ? (iou_out + grav_out + hm2) : hm_loss;
            }
        }
        if (t == 0) out[0] = (float)(tot * (1.0 / B_));
    }
}

// ---------------- launch ----------------
extern "C" void kernel_launch(void* const* d_in, const int* in_sizes, int n_in,
                              void* d_out, int out_size) {
    const float* keypoints = (const float*)d_in[0];
    const float* preg      = (const float*)d_in[1];
    const float* fpn       = (const float*)d_in[2];
    const float* gt        = (const float*)d_in[3];
    const float* masks     = (const float*)d_in[4];
    const float* sy        = (const float*)d_in[5];
    const float* sx        = (const float*)d_in[6];
    (void)in_sizes; (void)n_in; (void)out_size;

    fused_kernel<<<GRID_, 128>>>(keypoints, preg, fpn, masks, gt, sy, sx, (float*)d_out);
}